// round 9
// baseline (speedup 1.0000x reference)
#include <cuda_runtime.h>

// Problem constants
#define HH 256
#define WW 256
#define CC 64      // content/blur channels, also output channels of deform conv
#define BB 4
#define OC 18      // offset channels actually used (9 o-pairs)
#define HW (HH*WW)

typedef unsigned long long ull;

// ---------------------------------------------------------------------------
// f32x2 packed helpers (sm_103a FFMA2 path — only reachable via PTX)
// ---------------------------------------------------------------------------
__device__ __forceinline__ void ffma2(ull& d, ull a, ull b) {
    asm("fma.rn.f32x2 %0, %1, %2, %0;" : "+l"(d) : "l"(a), "l"(b));
}
__device__ __forceinline__ ull packf(float lo, float hi) {
    ull r; asm("mov.b64 %0, {%1, %2};" : "=l"(r) : "f"(lo), "f"(hi)); return r;
}
__device__ __forceinline__ void unpackf(ull v, float& lo, float& hi) {
    asm("mov.b64 {%0, %1}, %2;" : "=f"(lo), "=f"(hi) : "l"(v));
}

// Constant weight bank (15,360 B used) — reloaded between launches via async
// D2D memcpy-to-symbol nodes. Serves ~1/3 of weight pairs (constant port,
// LDC floor 8); the other ~2/3 come from smem (LDS floor 4, L1 pipe).
__constant__ ull c_wbank[3 * CC * 10];

// Staging buffers in global (filled by pack kernels)
__device__ ull g_wcst[9 * CC * 10];   // deform const-side pairs  [k][c][0..9]
__device__ ull g_wsm [9 * CC * 22];   // deform smem-side pairs   [k][c][10..31]
__device__ ull g_ocst[CC * 9 * 2];    // offset const-side pairs  [c*9+k][0..1]
__device__ ull g_osm [CC * 9 * 8];    // offset smem-side pairs   [c*9+k][2..9]

// ---------------------------------------------------------------------------
// Prelude packers
// ---------------------------------------------------------------------------
__global__ void wpack_deform(const float* __restrict__ dw)  // (64,64,3,3)
{
    int idx = blockIdx.x * blockDim.x + threadIdx.x;   // 0 .. 9*64*32-1
    int j = idx & 31;          // o-pair
    int c = (idx >> 5) & 63;
    int k = idx >> 11;
    float w0 = __ldg(dw + ((2 * j)     * CC + c) * 9 + k);
    float w1 = __ldg(dw + ((2 * j + 1) * CC + c) * 9 + k);
    ull v = packf(w0, w1);
    if (j < 10) g_wcst[(k * CC + c) * 10 + j]        = v;
    else        g_wsm [(k * CC + c) * 22 + (j - 10)] = v;
}

__global__ void wpack_off(const float* __restrict__ ow)     // (27,64,3,3)
{
    int idx = blockIdx.x * blockDim.x + threadIdx.x;   // 0 .. 64*9*10-1
    if (idx >= CC * 9 * 10) return;
    int j  = idx % 10;               // o-pair 0..9
    int ck = idx / 10;               // c*9 + k
    int o0 = 2 * j, o1 = 2 * j + 1;
    float w0 = (o0 < OC) ? __ldg(ow + o0 * (CC * 9) + ck) : 0.0f;
    float w1 = (o1 < OC) ? __ldg(ow + o1 * (CC * 9) + ck) : 0.0f;
    ull v = packf(w0, w1);
    if (j < 2) g_ocst[ck * 2 + j]       = v;
    else       g_osm [ck * 8 + (j - 2)] = v;
}

// ---------------------------------------------------------------------------
// Kernel A: 3x3 conv (pad 1): blur x offset_w -> offset (18 ch).
// Thread = pixel; 10 f32x2 o-pair accumulators (pair 9 is zero-padding).
// Per (c,k): 1 LDC.128 (pairs 0-1) + 4 LDS.128 (pairs 2-9) + 10 FFMA2.
// ---------------------------------------------------------------------------
__global__ __launch_bounds__(256, 4)
void offset_conv_kernel(const float* __restrict__ blur,
                        const float* __restrict__ ob,   // (27,)
                        float* __restrict__ off_out)    // (4,18,256,256)
{
    __shared__ ull s_ow[CC * 9 * 8];   // 36,864 B

    const int tid = threadIdx.x;
    {   // stage smem-side weights once (coalesced 16B copies)
        const ulonglong2* src = reinterpret_cast<const ulonglong2*>(g_osm);
        ulonglong2* dst = reinterpret_cast<ulonglong2*>(s_ow);
        for (int i = tid; i < CC * 9 * 4; i += blockDim.x)
            dst[i] = __ldg(src + i);
    }
    __syncthreads();

    const int p = blockIdx.x * blockDim.x + tid;
    const int x = p & (WW - 1);
    const int y = (p >> 8) & (HH - 1);
    const int b = p >> 16;

    ull acc[10];
#pragma unroll
    for (int j = 0; j < 10; j++) acc[j] = 0ull;

    const float* bp = blur + (size_t)b * CC * HW;
    const ulonglong2* cb2 = reinterpret_cast<const ulonglong2*>(c_wbank);
    const ulonglong2* sw2 = reinterpret_cast<const ulonglong2*>(s_ow);

    for (int c = 0; c < CC; c++) {
        const float* cp = bp + c * HW;
#pragma unroll
        for (int k = 0; k < 9; k++) {
            const int iy = y + k / 3 - 1;
            const int ix = x + k % 3 - 1;
            float v = 0.0f;
            if (iy >= 0 && iy < HH && ix >= 0 && ix < WW)
                v = __ldg(cp + iy * WW + ix);
            const ull vv = packf(v, v);
            const int ck = c * 9 + k;

            ulonglong2 wc = cb2[ck];             // pairs 0,1 (constant port)
            ffma2(acc[0], wc.x, vv);
            ffma2(acc[1], wc.y, vv);

            const ulonglong2* ws = sw2 + ck * 4; // pairs 2..9 (smem)
#pragma unroll
            for (int t = 0; t < 4; t++) {
                ulonglong2 w = ws[t];
                ffma2(acc[2 + 2 * t], w.x, vv);
                ffma2(acc[3 + 2 * t], w.y, vv);
            }
        }
    }

    float* op = off_out + ((size_t)b * OC) * HW + y * WW + x;
#pragma unroll
    for (int j = 0; j < OC / 2; j++) {   // pairs 0..8 cover o = 0..17
        float a0, a1;
        unpackf(acc[j], a0, a1);
        op[(2 * j)     * HW] = a0 + __ldg(ob + 2 * j);
        op[(2 * j + 1) * HW] = a1 + __ldg(ob + 2 * j + 1);
    }
}

// ---------------------------------------------------------------------------
// Kernel B: deformable conv, 3 taps per launch. Thread = pixel, interleaved
// gather + MAC. Weight pairs split: j=0..9 from constant bank (5 LDC.128/c),
// j=10..31 from smem (11 LDS.128/c), staged ONCE at kernel entry (33 KB,
// no per-k barriers). Both weight ports run below the FFMA2 floor.
// ---------------------------------------------------------------------------
__global__ __launch_bounds__(256, 2)
void deform_group_kernel(const float* __restrict__ content,
                         const float* __restrict__ offset,  // (4,18,256,256)
                         const float* __restrict__ db,      // (64,)
                         float* __restrict__ out,           // (4,64,256,256)
                         int k0, int first)
{
    __shared__ ull s_w[3 * CC * 22];   // 33,792 B

    const int tid = threadIdx.x;
    {   // stage smem-side weights for this tap group (coalesced)
        const ulonglong2* src = reinterpret_cast<const ulonglong2*>(
            g_wsm + (size_t)k0 * CC * 22);
        ulonglong2* dst = reinterpret_cast<ulonglong2*>(s_w);
        for (int i = tid; i < 3 * CC * 11; i += blockDim.x)
            dst[i] = __ldg(src + i);
    }
    __syncthreads();

    const int p = blockIdx.x * blockDim.x + tid;
    const int x = p & (WW - 1);
    const int y = (p >> 8) & (HH - 1);
    const int b = p >> 16;

    ull acc[32];                   // o-pair accumulators (64 channels)
#pragma unroll
    for (int j = 0; j < 32; j++) acc[j] = 0ull;

    const float* cb   = content + (size_t)b * CC * HW;
    const float* offb = offset + (size_t)b * OC * HW + y * WW + x;

#pragma unroll
    for (int kk = 0; kk < 3; kk++) {
        const int k = k0 + kk;

        const float offy = __ldg(offb + (2 * k) * HW);
        const float offx = __ldg(offb + (2 * k + 1) * HW);
        const float py = (float)(y + (k / 3) - 1) + offy;
        const float px = (float)(x + (k % 3) - 1) + offx;

        const float y0f = floorf(py);
        const float x0f = floorf(px);
        const float wy = py - y0f;
        const float wx = px - x0f;
        const int iy0 = (int)y0f, ix0 = (int)x0f;
        const int iy1 = iy0 + 1,  ix1 = ix0 + 1;

        const bool vy0 = (iy0 >= 0) && (iy0 < HH);
        const bool vy1 = (iy1 >= 0) && (iy1 < HH);
        const bool vx0 = (ix0 >= 0) && (ix0 < WW);
        const bool vx1 = (ix1 >= 0) && (ix1 < WW);

        const float w00 = (1.f - wy) * (1.f - wx) * ((vy0 && vx0) ? 1.f : 0.f);
        const float w01 = (1.f - wy) * wx         * ((vy0 && vx1) ? 1.f : 0.f);
        const float w10 = wy * (1.f - wx)         * ((vy1 && vx0) ? 1.f : 0.f);
        const float w11 = wy * wx                 * ((vy1 && vx1) ? 1.f : 0.f);

        const int cy0 = min(max(iy0, 0), HH - 1);
        const int cy1 = min(max(iy1, 0), HH - 1);
        const int cx0 = min(max(ix0, 0), WW - 1);
        const int cx1 = min(max(ix1, 0), WW - 1);

        const float* p00 = cb + cy0 * WW + cx0;
        const float* p01 = cb + cy0 * WW + cx1;
        const float* p10 = cb + cy1 * WW + cx0;
        const float* p11 = cb + cy1 * WW + cx1;

        const ulonglong2* cbank = reinterpret_cast<const ulonglong2*>(c_wbank)
                                + kk * (CC * 5);
        const ulonglong2* sbank = reinterpret_cast<const ulonglong2*>(s_w)
                                + kk * (CC * 11);

#pragma unroll 2
        for (int c = 0; c < CC; c++) {
            const int co = c * HW;
            const float samp = w00 * __ldg(p00 + co)
                             + w01 * __ldg(p01 + co)
                             + w10 * __ldg(p10 + co)
                             + w11 * __ldg(p11 + co);
            const ull vv = packf(samp, samp);

            const ulonglong2* wc = cbank + c * 5;   // pairs 0..9 (constant)
#pragma unroll
            for (int t = 0; t < 5; t++) {
                ulonglong2 w = wc[t];
                ffma2(acc[2 * t],     w.x, vv);
                ffma2(acc[2 * t + 1], w.y, vv);
            }
            const ulonglong2* ws = sbank + c * 11;  // pairs 10..31 (smem)
#pragma unroll
            for (int t = 0; t < 11; t++) {
                ulonglong2 w = ws[t];
                ffma2(acc[10 + 2 * t], w.x, vv);
                ffma2(acc[11 + 2 * t], w.y, vv);
            }
        }
    }

    // epilogue: unpack 32 o-pairs -> 64 channels, coalesced
    float* op = out + (size_t)b * CC * HW + y * WW + x;
    if (first) {
#pragma unroll
        for (int j = 0; j < 32; j++) {
            float a0, a1;
            unpackf(acc[j], a0, a1);
            op[(2 * j)     * HW] = a0 + __ldg(db + 2 * j);
            op[(2 * j + 1) * HW] = a1 + __ldg(db + 2 * j + 1);
        }
    } else {
#pragma unroll
        for (int j = 0; j < 32; j++) {
            float a0, a1;
            unpackf(acc[j], a0, a1);
            op[(2 * j)     * HW] += a0;
            op[(2 * j + 1) * HW] += a1;
        }
    }
}

// ---------------------------------------------------------------------------
// kernel_launch
//   d_in[0] content_feats (4,64,256,256) f32
//   d_in[1] blur_feats    (4,64,256,256) f32
//   d_in[2] offset_w      (27,64,3,3)    f32
//   d_in[3] offset_b      (27,)          f32
//   d_in[4] dc_w          (64,64,3,3)    f32
//   d_in[5] dc_b          (64,)          f32
// d_out = [ out (4,64,256,256) | offset (4,18,256,256) ]
// ---------------------------------------------------------------------------
extern "C" void kernel_launch(void* const* d_in, const int* in_sizes, int n_in,
                              void* d_out, int out_size)
{
    const float* content = (const float*)d_in[0];
    const float* blur    = (const float*)d_in[1];
    const float* ow      = (const float*)d_in[2];
    const float* ob      = (const float*)d_in[3];
    const float* dw      = (const float*)d_in[4];
    const float* db      = (const float*)d_in[5];

    float* out     = (float*)d_out;
    float* off_out = out + (size_t)BB * CC * HW;

    void* wcst_addr = nullptr;
    void* ocst_addr = nullptr;
    cudaGetSymbolAddress(&wcst_addr, g_wcst);
    cudaGetSymbolAddress(&ocst_addr, g_ocst);
    const ull* wcst_p = (const ull*)wcst_addr;

    // 1) pack weights into split pair layouts
    wpack_deform<<<(9 * CC * 32) / 256, 256>>>(dw);
    wpack_off<<<(CC * 9 * 10 + 255) / 256, 256>>>(ow);

    // 2) offset conv (const side: 2 pairs per (c,k))
    cudaMemcpyToSymbolAsync(c_wbank, ocst_addr,
                            (size_t)CC * 9 * 2 * sizeof(ull), 0,
                            cudaMemcpyDeviceToDevice, 0);
    offset_conv_kernel<<<(BB * HW) / 256, 256>>>(blur, ob, off_out);

    // 3) deform conv in 3 tap-groups; const bank reloaded per group
    const size_t grp_bytes = (size_t)3 * CC * 10 * sizeof(ull);   // 15,360
    for (int g = 0; g < 3; g++) {
        cudaMemcpyToSymbolAsync(c_wbank, wcst_p + (size_t)g * 3 * CC * 10,
                                grp_bytes, 0, cudaMemcpyDeviceToDevice, 0);
        deform_group_kernel<<<(BB * HW) / 256, 256>>>(
            content, off_out, db, out, 3 * g, g == 0 ? 1 : 0);
    }
}